// round 15
// baseline (speedup 1.0000x reference)
#include <cuda_runtime.h>

// Problem constants (fixed by the reference)
#define NN 50000
#define EE 800000
#define HH 64
#define GG 256

#define SC_NB 52                 // scan blocks
#define CNT_PAD (SC_NB * 1024)   // 53248 (padded count array)

typedef unsigned long long u64;

// ---------------- scratch (device globals; no runtime allocation) ----------
__device__ float g_q[NN * HH];
__device__ float g_k[NN * HH];
__device__ float g_v[NN * HH];
__device__ float g_s[NN * HH];   // skip = in @ Ws + bs
__device__ float g_h[NN * HH];   // layer-1 output

__device__ int   g_cnt[CNT_PAD];      // per-dst edge counts (padded)
__device__ int   g_off[CNT_PAD + 4];  // CSR row offsets
__device__ int   g_off2[CNT_PAD + 4]; // scatter cursors (copy of offsets)
__device__ int   g_bsum[SC_NB];       // scan phase A partials
__device__ int   g_bbase[SC_NB];      // scan phase B bases
__device__ int   g_csrc[EE];          // CSR: src node per edge slot
__device__ float g_cw[EE];            // CSR: edge weight per edge slot

__device__ float g_pool[GG * HH];
__device__ float g_pcnt[GG];

// ---------------- packed f32x2 helpers --------------------------------------
__device__ __forceinline__ u64 pack2(float lo, float hi) {
    u64 r; asm("mov.b64 %0, {%1, %2};" : "=l"(r) : "f"(lo), "f"(hi)); return r;
}
__device__ __forceinline__ void fma2(u64& d, u64 a, u64 b) {
    asm("fma.rn.f32x2 %0, %1, %2, %0;" : "+l"(d) : "l"(a), "l"(b));
}
__device__ __forceinline__ float2 unpack2(u64 v) {
    float2 r; asm("mov.b64 {%0, %1}, %2;" : "=f"(r.x), "=f"(r.y) : "l"(v)); return r;
}

// ---------------- zero scratch (vectorized) ---------------------------------
__global__ void zero_kernel() {
    int i = blockIdx.x * blockDim.x + threadIdx.x;
    const int C4 = CNT_PAD / 4;          // 13312
    const int P4 = (GG * HH) / 4;        // 4096
    const int T  = C4 + P4 + GG / 4;     // 17472
    for (; i < T; i += gridDim.x * blockDim.x) {
        if (i < C4)           ((int4*)g_cnt)[i] = make_int4(0, 0, 0, 0);
        else if (i < C4 + P4) ((float4*)g_pool)[i - C4] = make_float4(0, 0, 0, 0);
        else                  ((float4*)g_pcnt)[i - C4 - P4] = make_float4(0, 0, 0, 0);
    }
}

// ---------------- CSR counts + graph node counts (int4 loads) --------------
__global__ void count_kernel(const int* __restrict__ ei,
                             const int* __restrict__ batch) {
    int t = blockIdx.x * blockDim.x + threadIdx.x;
    const int NE4 = EE / 4;       // 200000
    const int NB4 = NN / 4;       // 12500
    if (t < NE4) {
        int4 d = ((const int4*)(ei + EE))[t];
        atomicAdd(&g_cnt[d.x], 1);
        atomicAdd(&g_cnt[d.y], 1);
        atomicAdd(&g_cnt[d.z], 1);
        atomicAdd(&g_cnt[d.w], 1);
    } else if (t < NE4 + NB4) {
        int4 b = ((const int4*)batch)[t - NE4];
        atomicAdd(&g_pcnt[b.x], 1.f);
        atomicAdd(&g_pcnt[b.y], 1.f);
        atomicAdd(&g_pcnt[b.z], 1.f);
        atomicAdd(&g_pcnt[b.w], 1.f);
    }
}

// ---------------- parallel exclusive scan: 3 phases --------------------------
__global__ void scanA_kernel() {
    __shared__ int wsum[8];
    const int b = blockIdx.x, t = threadIdx.x;
    int4 v = ((const int4*)g_cnt)[b * 256 + t];
    int s = v.x + v.y + v.z + v.w;
#pragma unroll
    for (int o = 16; o; o >>= 1) s += __shfl_xor_sync(0xffffffffu, s, o);
    if ((t & 31) == 0) wsum[t >> 5] = s;
    __syncthreads();
    if (t < 8) {
        int x = wsum[t];
#pragma unroll
        for (int o = 4; o; o >>= 1) x += __shfl_xor_sync(0xffu, x, o);
        if (t == 0) g_bsum[b] = x;
    }
}

__global__ void scanB_kernel() {
    __shared__ int sh[64];
    const int t = threadIdx.x;
    int v = (t < SC_NB) ? g_bsum[t] : 0;
    sh[t] = v;
    __syncthreads();
    for (int o = 1; o < 64; o <<= 1) {
        int u = (t >= o) ? sh[t - o] : 0;
        __syncthreads();
        sh[t] += u;
        __syncthreads();
    }
    if (t < SC_NB) g_bbase[t] = sh[t] - v;   // exclusive
}

__global__ void scanC_kernel() {
    __shared__ int wpre[8];
    const int b = blockIdx.x, t = threadIdx.x;
    const int lane = t & 31, w = t >> 5;
    int4 v = ((const int4*)g_cnt)[b * 256 + t];
    int s = v.x + v.y + v.z + v.w;

    int ps = s;  // inclusive warp scan of per-thread sums
#pragma unroll
    for (int o = 1; o < 32; o <<= 1) {
        int u = __shfl_up_sync(0xffffffffu, ps, o);
        if (lane >= o) ps += u;
    }
    if (lane == 31) wpre[w] = ps;
    __syncthreads();
    if (t < 8) {
        int x = wpre[t];
        int px = x;
#pragma unroll
        for (int o = 1; o < 8; o <<= 1) {
            int u = __shfl_up_sync(0xffu, px, o);
            if (t >= o) px += u;
        }
        wpre[t] = px - x;
    }
    __syncthreads();

    int base = g_bbase[b] + wpre[w] + (ps - s);
    int4 o;
    o.x = base;
    o.y = base + v.x;
    o.z = o.y + v.y;
    o.w = o.z + v.z;
    ((int4*)g_off)[b * 256 + t]  = o;
    ((int4*)g_off2)[b * 256 + t] = o;
    if (b == SC_NB - 1 && t == 255) g_off[CNT_PAD] = o.w + v.w;
}

// ---------------- scatter into CSR (cursor = offset copy) -------------------
__global__ void scatter_kernel(const int* __restrict__ ei,
                               const float* __restrict__ ew) {
    int t = blockIdx.x * blockDim.x + threadIdx.x;
    if (t >= EE / 4) return;
    int4   s4 = ((const int4*)ei)[t];
    int4   d4 = ((const int4*)(ei + EE))[t];
    float4 w4 = ((const float4*)ew)[t];
    int p;
    p = atomicAdd(&g_off2[d4.x], 1); g_csrc[p] = s4.x; g_cw[p] = w4.x;
    p = atomicAdd(&g_off2[d4.y], 1); g_csrc[p] = s4.y; g_cw[p] = w4.y;
    p = atomicAdd(&g_off2[d4.z], 1); g_csrc[p] = s4.z; g_cw[p] = w4.z;
    p = atomicAdd(&g_off2[d4.w], 1); g_csrc[p] = s4.w; g_cw[p] = w4.w;
}

// ---------------- fused 4-matrix GEMM (FFMA2, pre-duplicated x) -------------
// out{q,k,v,s}[n] = in[n] @ W{q,k,v,s} + b.  Tile: 64 nodes x 256 feats.
// 512 threads; thread = 8 nodes x 4 feats.  x tile stored as (x,x) f32x2 in
// smem (packed ONCE at load) so the inner loop has zero mov.b64 packs:
// 4 LDS.128 (x, broadcast) + 1 LDS.128 (w) + 16 FFMA2 per k-step.
// Row stride is EVEN (66 u64) so all ulonglong2 accesses stay 16B-aligned
// (stride 65 -> odd kk row gave addr%16==8 -> misaligned trap in R13).
#define XST2_STRIDE 66                                      // u64 units, even
#define GEMM_SMEM (64 * 256 * 4 + 64 * XST2_STRIDE * 8)     // 99328 bytes

__global__ __launch_bounds__(512, 2) void gemm4_kernel(
    const float* __restrict__ xin, int use_h,
    const float* __restrict__ Wq, const float* __restrict__ bq,
    const float* __restrict__ Wk, const float* __restrict__ bk,
    const float* __restrict__ Wv, const float* __restrict__ bv,
    const float* __restrict__ Ws, const float* __restrict__ bs) {
    extern __shared__ char smem[];
    float* Wsh = (float*)smem;                 // [64][256]: q|k|v|s concat
    u64*   xst2 = (u64*)(smem + 64 * 256 * 4); // [64][66] duplicated x pairs

    const float* in = use_h ? g_h : xin;
    const int t   = threadIdx.x;
    const int n0g = blockIdx.x * 64;

    // Load weights: Wsh[kk][mat*64 + f]
    for (int i = t; i < 4096; i += 512) {
        int kk = i >> 6, f = i & 63;
        float* row = &Wsh[kk * 256];
        row[f]       = Wq[i];
        row[64 + f]  = Wk[i];
        row[128 + f] = Wv[i];
        row[192 + f] = Ws[i];
    }
    // Load x tile transposed + duplicated: xst2[kk][nl] = (x, x)
    for (int i = t; i < 4096; i += 512) {
        int nl = i >> 6, kk = i & 63;
        int n = n0g + nl;
        float v = (n < NN) ? in[n * 64 + kk] : 0.f;
        xst2[kk * XST2_STRIDE + nl] = pack2(v, v);
    }
    __syncthreads();

    const int warp = t >> 5;
    const int l    = t & 31;
    const int fgrp = warp & 1;            // 0: q|k feats, 1: v|s feats
    const int fA   = fgrp * 128 + l * 4;  // position in 256-wide concat
    const int n0   = (warp >> 1) * 8;     // node octet

    u64 acc2[8][2];
#pragma unroll
    for (int i = 0; i < 8; i++) { acc2[i][0] = 0ULL; acc2[i][1] = 0ULL; }

#pragma unroll 4
    for (int kk = 0; kk < 64; kk++) {
        const u64* xr = &xst2[kk * XST2_STRIDE + n0];
        ulonglong2 x01 = *(const ulonglong2*)xr;
        ulonglong2 x23 = *(const ulonglong2*)(xr + 2);
        ulonglong2 x45 = *(const ulonglong2*)(xr + 4);
        ulonglong2 x67 = *(const ulonglong2*)(xr + 6);
        ulonglong2 w2 = *(const ulonglong2*)(&Wsh[kk * 256] + fA);
        u64 xd[8] = {x01.x, x01.y, x23.x, x23.y, x45.x, x45.y, x67.x, x67.y};
#pragma unroll
        for (int i = 0; i < 8; i++) {
            fma2(acc2[i][0], xd[i], w2.x);
            fma2(acc2[i][1], xd[i], w2.y);
        }
    }

    // Output routing: matsel = fgrp*2 + (l>>4): 0=q, 1=k, 2=v, 3=s
    const int fo = (l & 15) * 4;
    float* op;  const float* bp;
    if (fgrp == 0) { if (l < 16) { op = g_q; bp = bq; } else { op = g_k; bp = bk; } }
    else           { if (l < 16) { op = g_v; bp = bv; } else { op = g_s; bp = bs; } }
    float4 bias = *(const float4*)&bp[fo];

#pragma unroll
    for (int i = 0; i < 8; i++) {
        int n = n0g + n0 + i;
        if (n < NN) {
            float2 p0 = unpack2(acc2[i][0]);
            float2 p1 = unpack2(acc2[i][1]);
            float4 r;
            r.x = p0.x + bias.x; r.y = p0.y + bias.y;
            r.z = p1.x + bias.z; r.w = p1.y + bias.w;
            *(float4*)&op[n * 64 + fo] = r;
        }
    }
}

// ---------------- edge aggregation: half-warp per edge, direct softmax ------
// (R8-identical: the best-measured aggregation variant.)
__global__ __launch_bounds__(256) void edge_agg_kernel(
    const float* __restrict__ We, int do_pool, const int* __restrict__ batch) {
    int wid  = (blockIdx.x * blockDim.x + threadIdx.x) >> 5;
    int lane = threadIdx.x & 31;
    if (wid >= NN) return;
    const int dst  = wid;
    const int half = lane >> 4;
    const int f0   = (lane & 15) * 4;
    const unsigned hmask = half ? 0xFFFF0000u : 0x0000FFFFu;

    const float4 q4  = *(const float4*)&g_q[dst * 64 + f0];
    const float4 we4 = *(const float4*)&We[f0];

    float p = q4.x * we4.x + q4.y * we4.y + q4.z * we4.z + q4.w * we4.w;
#pragma unroll
    for (int o = 8; o; o >>= 1) p += __shfl_xor_sync(hmask, p, o);
    const float qwe = p;

    const int i0 = g_off[dst], i1 = g_off[dst + 1];
    float s = 0.f, spw = 0.f;
    float a0 = 0.f, a1 = 0.f, a2 = 0.f, a3 = 0.f;

    for (int i = i0 + half; i < i1; i += 2) {
        int   src = g_csrc[i];
        float w   = g_cw[i];
        const float4 k4 = *(const float4*)&g_k[src * 64 + f0];
        const float4 v4 = *(const float4*)&g_v[src * 64 + f0];
        float d = q4.x * k4.x + q4.y * k4.y + q4.z * k4.z + q4.w * k4.w;
#pragma unroll
        for (int o = 8; o; o >>= 1) d += __shfl_xor_sync(hmask, d, o);
        float pe = __expf((d + w * qwe) * 0.125f);   // 1/sqrt(64)

        s   += pe;
        spw += pe * w;
        a0  += pe * v4.x;
        a1  += pe * v4.y;
        a2  += pe * v4.z;
        a3  += pe * v4.w;
    }

    s   += __shfl_xor_sync(0xffffffffu, s,   16);
    spw += __shfl_xor_sync(0xffffffffu, spw, 16);
    a0  += __shfl_xor_sync(0xffffffffu, a0,  16);
    a1  += __shfl_xor_sync(0xffffffffu, a1,  16);
    a2  += __shfl_xor_sync(0xffffffffu, a2,  16);
    a3  += __shfl_xor_sync(0xffffffffu, a3,  16);

    float inv = 1.f / (s + 1e-16f);
    const float4 sk = *(const float4*)&g_s[dst * 64 + f0];
    float o0 = fmaxf((a0 + spw * we4.x) * inv + sk.x, 0.f);
    float o1 = fmaxf((a1 + spw * we4.y) * inv + sk.y, 0.f);
    float o2 = fmaxf((a2 + spw * we4.z) * inv + sk.z, 0.f);
    float o3 = fmaxf((a3 + spw * we4.w) * inv + sk.w, 0.f);

    if (half == 0) {
        if (do_pool) {
            int g = batch[dst];
            float* pp = &g_pool[g * 64 + f0];
            atomicAdd(pp,     o0);
            atomicAdd(pp + 1, o1);
            atomicAdd(pp + 2, o2);
            atomicAdd(pp + 3, o3);
        } else {
            float4 o; o.x = o0; o.y = o1; o.z = o2; o.w = o3;
            *(float4*)&g_h[dst * 64 + f0] = o;
        }
    }
}

// ---------------- classifier head ------------------------------------------
__global__ void final_kernel(const float* __restrict__ Wl,
                             const float* __restrict__ bl,
                             float* __restrict__ out) {
    int t = threadIdx.x;  // 512 = GG * 2
    int g = t >> 1, c = t & 1;
    float cnt = fmaxf(g_pcnt[g], 1.f);
    float sum = 0.f;
    for (int f = 0; f < 64; f++)
        sum += g_pool[g * 64 + f] * Wl[f * 2 + c];
    out[g * 2 + c] = sum / cnt + bl[c];
}

// ---------------- launch ----------------------------------------------------
extern "C" void kernel_launch(void* const* d_in, const int* in_sizes, int n_in,
                              void* d_out, int out_size) {
    const float* x     = (const float*)d_in[0];
    const int*   ei    = (const int*)d_in[1];
    const float* ew    = (const float*)d_in[2];
    const int*   batch = (const int*)d_in[3];
    const float *Wq1 = (const float*)d_in[4],  *bq1 = (const float*)d_in[5];
    const float *Wk1 = (const float*)d_in[6],  *bk1 = (const float*)d_in[7];
    const float *Wv1 = (const float*)d_in[8],  *bv1 = (const float*)d_in[9];
    const float *We1 = (const float*)d_in[10];
    const float *Ws1 = (const float*)d_in[11], *bs1 = (const float*)d_in[12];
    const float *Wq2 = (const float*)d_in[13], *bq2 = (const float*)d_in[14];
    const float *Wk2 = (const float*)d_in[15], *bk2 = (const float*)d_in[16];
    const float *Wv2 = (const float*)d_in[17], *bv2 = (const float*)d_in[18];
    const float *We2 = (const float*)d_in[19];
    const float *Ws2 = (const float*)d_in[20], *bs2 = (const float*)d_in[21];
    const float *Wl  = (const float*)d_in[22], *bl  = (const float*)d_in[23];
    float* out = (float*)d_out;

    cudaFuncSetAttribute(gemm4_kernel,
                         cudaFuncAttributeMaxDynamicSharedMemorySize, GEMM_SMEM);

    const int GEMM_BLOCKS  = (NN + 63) / 64;                     // 782
    const int COUNT_BLOCKS = (EE / 4 + NN / 4 + 255) / 256;      // 831
    const int SCAT_BLOCKS  = (EE / 4 + 255) / 256;               // 782
    const int AGG_BLOCKS   = (NN * 32 + 255) / 256;              // 6250

    // CSR build; gemm1 kept as 4th launch (profiled slot, independent of CSR)
    zero_kernel<<<69, 256>>>();
    count_kernel<<<COUNT_BLOCKS, 256>>>(ei, batch);
    scanA_kernel<<<SC_NB, 256>>>();
    gemm4_kernel<<<GEMM_BLOCKS, 512, GEMM_SMEM>>>(x, 0, Wq1, bq1, Wk1, bk1,
                                                  Wv1, bv1, Ws1, bs1);
    scanB_kernel<<<1, 64>>>();
    scanC_kernel<<<SC_NB, 256>>>();
    scatter_kernel<<<SCAT_BLOCKS, 256>>>(ei, ew);

    // Layer 1 aggregation
    edge_agg_kernel<<<AGG_BLOCKS, 256>>>(We1, 0, batch);

    // Layer 2 (input = g_h; pooling fused, h never materialized)
    gemm4_kernel<<<GEMM_BLOCKS, 512, GEMM_SMEM>>>(x, 1, Wq2, bq2, Wk2, bk2,
                                                  Wv2, bv2, Ws2, bs2);
    edge_agg_kernel<<<AGG_BLOCKS, 256>>>(We2, 1, batch);

    // Head
    final_kernel<<<1, 512>>>(Wl, bl, out);
}

// round 16
// speedup vs baseline: 1.5173x; 1.5173x over previous
#include <cuda_runtime.h>

// Problem constants (fixed by the reference)
#define NN 50000
#define EE 800000
#define HH 64
#define GG 256

#define SC_NB 52                 // scan blocks
#define CNT_PAD (SC_NB * 1024)   // 53248 (padded count array)

typedef unsigned long long u64;

// ---------------- scratch (device globals; no runtime allocation) ----------
__device__ float g_q[NN * HH];
__device__ float g_k[NN * HH];
__device__ float g_v[NN * HH];
__device__ float g_s[NN * HH];   // skip = in @ Ws + bs
__device__ float g_h[NN * HH];   // layer-1 output

__device__ int   g_cnt[CNT_PAD];      // per-dst edge counts (padded)
__device__ int   g_off[CNT_PAD + 4];  // CSR row offsets
__device__ int   g_off2[CNT_PAD + 4]; // scatter cursors (copy of offsets)
__device__ int   g_bsum[SC_NB];       // scan phase A partials
__device__ int   g_bbase[SC_NB];      // scan phase B bases
__device__ int   g_csrc[EE];          // CSR: src node per edge slot
__device__ float g_cw[EE];            // CSR: edge weight per edge slot

__device__ float g_pool[GG * HH];
__device__ float g_pcnt[GG];

// ---------------- packed f32x2 helpers --------------------------------------
__device__ __forceinline__ u64 pack2(float lo, float hi) {
    u64 r; asm("mov.b64 %0, {%1, %2};" : "=l"(r) : "f"(lo), "f"(hi)); return r;
}
__device__ __forceinline__ void fma2(u64& d, u64 a, u64 b) {
    asm("fma.rn.f32x2 %0, %1, %2, %0;" : "+l"(d) : "l"(a), "l"(b));
}
__device__ __forceinline__ float2 unpack2(u64 v) {
    float2 r; asm("mov.b64 {%0, %1}, %2;" : "=f"(r.x), "=f"(r.y) : "l"(v)); return r;
}

// ---------------- zero scratch (vectorized) ---------------------------------
__global__ void zero_kernel() {
    int i = blockIdx.x * blockDim.x + threadIdx.x;
    const int C4 = CNT_PAD / 4;          // 13312
    const int P4 = (GG * HH) / 4;        // 4096
    const int T  = C4 + P4 + GG / 4;     // 17472
    for (; i < T; i += gridDim.x * blockDim.x) {
        if (i < C4)           ((int4*)g_cnt)[i] = make_int4(0, 0, 0, 0);
        else if (i < C4 + P4) ((float4*)g_pool)[i - C4] = make_float4(0, 0, 0, 0);
        else                  ((float4*)g_pcnt)[i - C4 - P4] = make_float4(0, 0, 0, 0);
    }
}

// ---------------- CSR counts + graph node counts (int4 loads) --------------
__global__ void count_kernel(const int* __restrict__ ei,
                             const int* __restrict__ batch) {
    int t = blockIdx.x * blockDim.x + threadIdx.x;
    const int NE4 = EE / 4;       // 200000
    const int NB4 = NN / 4;       // 12500
    if (t < NE4) {
        int4 d = ((const int4*)(ei + EE))[t];
        atomicAdd(&g_cnt[d.x], 1);
        atomicAdd(&g_cnt[d.y], 1);
        atomicAdd(&g_cnt[d.z], 1);
        atomicAdd(&g_cnt[d.w], 1);
    } else if (t < NE4 + NB4) {
        int4 b = ((const int4*)batch)[t - NE4];
        atomicAdd(&g_pcnt[b.x], 1.f);
        atomicAdd(&g_pcnt[b.y], 1.f);
        atomicAdd(&g_pcnt[b.z], 1.f);
        atomicAdd(&g_pcnt[b.w], 1.f);
    }
}

// ---------------- parallel exclusive scan: 3 phases --------------------------
__global__ void scanA_kernel() {
    __shared__ int wsum[8];
    const int b = blockIdx.x, t = threadIdx.x;
    int4 v = ((const int4*)g_cnt)[b * 256 + t];
    int s = v.x + v.y + v.z + v.w;
#pragma unroll
    for (int o = 16; o; o >>= 1) s += __shfl_xor_sync(0xffffffffu, s, o);
    if ((t & 31) == 0) wsum[t >> 5] = s;
    __syncthreads();
    if (t < 8) {
        int x = wsum[t];
#pragma unroll
        for (int o = 4; o; o >>= 1) x += __shfl_xor_sync(0xffu, x, o);
        if (t == 0) g_bsum[b] = x;
    }
}

__global__ void scanB_kernel() {
    __shared__ int sh[64];
    const int t = threadIdx.x;
    int v = (t < SC_NB) ? g_bsum[t] : 0;
    sh[t] = v;
    __syncthreads();
    for (int o = 1; o < 64; o <<= 1) {
        int u = (t >= o) ? sh[t - o] : 0;
        __syncthreads();
        sh[t] += u;
        __syncthreads();
    }
    if (t < SC_NB) g_bbase[t] = sh[t] - v;   // exclusive
}

__global__ void scanC_kernel() {
    __shared__ int wpre[8];
    const int b = blockIdx.x, t = threadIdx.x;
    const int lane = t & 31, w = t >> 5;
    int4 v = ((const int4*)g_cnt)[b * 256 + t];
    int s = v.x + v.y + v.z + v.w;

    int ps = s;  // inclusive warp scan of per-thread sums
#pragma unroll
    for (int o = 1; o < 32; o <<= 1) {
        int u = __shfl_up_sync(0xffffffffu, ps, o);
        if (lane >= o) ps += u;
    }
    if (lane == 31) wpre[w] = ps;
    __syncthreads();
    if (t < 8) {
        int x = wpre[t];
        int px = x;
#pragma unroll
        for (int o = 1; o < 8; o <<= 1) {
            int u = __shfl_up_sync(0xffu, px, o);
            if (t >= o) px += u;
        }
        wpre[t] = px - x;
    }
    __syncthreads();

    int base = g_bbase[b] + wpre[w] + (ps - s);
    int4 o;
    o.x = base;
    o.y = base + v.x;
    o.z = o.y + v.y;
    o.w = o.z + v.z;
    ((int4*)g_off)[b * 256 + t]  = o;
    ((int4*)g_off2)[b * 256 + t] = o;
    if (b == SC_NB - 1 && t == 255) g_off[CNT_PAD] = o.w + v.w;
}

// ---------------- scatter into CSR (cursor = offset copy) -------------------
__global__ void scatter_kernel(const int* __restrict__ ei,
                               const float* __restrict__ ew) {
    int t = blockIdx.x * blockDim.x + threadIdx.x;
    if (t >= EE / 4) return;
    int4   s4 = ((const int4*)ei)[t];
    int4   d4 = ((const int4*)(ei + EE))[t];
    float4 w4 = ((const float4*)ew)[t];
    int p;
    p = atomicAdd(&g_off2[d4.x], 1); g_csrc[p] = s4.x; g_cw[p] = w4.x;
    p = atomicAdd(&g_off2[d4.y], 1); g_csrc[p] = s4.y; g_cw[p] = w4.y;
    p = atomicAdd(&g_off2[d4.z], 1); g_csrc[p] = s4.z; g_cw[p] = w4.z;
    p = atomicAdd(&g_off2[d4.w], 1); g_csrc[p] = s4.w; g_cw[p] = w4.w;
}

// ---------------- fused 4-matrix GEMM (packed f32x2 FFMA, 512 thr) ----------
// R11-verbatim: the measured-best GEMM (58us). Tile: 64 nodes x 256 feats.
// 512 threads; thread = 8 nodes x 4 feats. 2 blocks/SM -> 32 warps/SM.
#define GEMM_SMEM (64 * 256 * 4 + 64 * 68 * 4)   // 82944 bytes

__global__ __launch_bounds__(512, 2) void gemm4_kernel(
    const float* __restrict__ xin, int use_h,
    const float* __restrict__ Wq, const float* __restrict__ bq,
    const float* __restrict__ Wk, const float* __restrict__ bk,
    const float* __restrict__ Wv, const float* __restrict__ bv,
    const float* __restrict__ Ws, const float* __restrict__ bs) {
    extern __shared__ float smem[];
    float* Wsh = smem;              // [64][256]: q|k|v|s concat per k-row
    float* xst = smem + 64 * 256;   // [64][68]  (transposed x tile, padded)

    const float* in = use_h ? g_h : xin;
    const int t   = threadIdx.x;
    const int n0g = blockIdx.x * 64;

    for (int i = t; i < 4096; i += 512) {
        int kk = i >> 6, f = i & 63;
        float* row = &Wsh[kk * 256];
        row[f]       = Wq[i];
        row[64 + f]  = Wk[i];
        row[128 + f] = Wv[i];
        row[192 + f] = Ws[i];
    }
    for (int i = t; i < 4096; i += 512) {
        int nl = i >> 6, kk = i & 63;
        int n = n0g + nl;
        xst[kk * 68 + nl] = (n < NN) ? in[n * 64 + kk] : 0.f;
    }
    __syncthreads();

    const int warp = t >> 5;
    const int l    = t & 31;
    const int fgrp = warp & 1;            // 0: q|k feats, 1: v|s feats
    const int fA   = fgrp * 128 + l * 4;  // position in 256-wide concat
    const int n0   = (warp >> 1) * 8;     // node octet

    u64 acc2[8][2];
#pragma unroll
    for (int i = 0; i < 8; i++) { acc2[i][0] = 0ULL; acc2[i][1] = 0ULL; }

#pragma unroll 4
    for (int kk = 0; kk < 64; kk++) {
        const float* xr = &xst[kk * 68 + n0];
        float4 xa = *(const float4*)xr;
        float4 xb = *(const float4*)(xr + 4);
        ulonglong2 w2 = *(const ulonglong2*)(&Wsh[kk * 256] + fA);
        float xv[8] = {xa.x, xa.y, xa.z, xa.w, xb.x, xb.y, xb.z, xb.w};
#pragma unroll
        for (int i = 0; i < 8; i++) {
            u64 xd = pack2(xv[i], xv[i]);
            fma2(acc2[i][0], xd, w2.x);
            fma2(acc2[i][1], xd, w2.y);
        }
    }

    const int fo = (l & 15) * 4;
    float* op;  const float* bp;
    if (fgrp == 0) { if (l < 16) { op = g_q; bp = bq; } else { op = g_k; bp = bk; } }
    else           { if (l < 16) { op = g_v; bp = bv; } else { op = g_s; bp = bs; } }
    float4 bias = *(const float4*)&bp[fo];

#pragma unroll
    for (int i = 0; i < 8; i++) {
        int n = n0g + n0 + i;
        if (n < NN) {
            float2 p0 = unpack2(acc2[i][0]);
            float2 p1 = unpack2(acc2[i][1]);
            float4 r;
            r.x = p0.x + bias.x; r.y = p0.y + bias.y;
            r.z = p1.x + bias.z; r.w = p1.y + bias.w;
            *(float4*)&op[n * 64 + fo] = r;
        }
    }
}

// ---------------- edge aggregation: half-warp per edge, direct softmax ------
// (R8-identical: the best-measured aggregation variant.)
__global__ __launch_bounds__(256) void edge_agg_kernel(
    const float* __restrict__ We, int do_pool, const int* __restrict__ batch) {
    int wid  = (blockIdx.x * blockDim.x + threadIdx.x) >> 5;
    int lane = threadIdx.x & 31;
    if (wid >= NN) return;
    const int dst  = wid;
    const int half = lane >> 4;
    const int f0   = (lane & 15) * 4;
    const unsigned hmask = half ? 0xFFFF0000u : 0x0000FFFFu;

    const float4 q4  = *(const float4*)&g_q[dst * 64 + f0];
    const float4 we4 = *(const float4*)&We[f0];

    float p = q4.x * we4.x + q4.y * we4.y + q4.z * we4.z + q4.w * we4.w;
#pragma unroll
    for (int o = 8; o; o >>= 1) p += __shfl_xor_sync(hmask, p, o);
    const float qwe = p;

    const int i0 = g_off[dst], i1 = g_off[dst + 1];
    float s = 0.f, spw = 0.f;
    float a0 = 0.f, a1 = 0.f, a2 = 0.f, a3 = 0.f;

    for (int i = i0 + half; i < i1; i += 2) {
        int   src = g_csrc[i];
        float w   = g_cw[i];
        const float4 k4 = *(const float4*)&g_k[src * 64 + f0];
        const float4 v4 = *(const float4*)&g_v[src * 64 + f0];
        float d = q4.x * k4.x + q4.y * k4.y + q4.z * k4.z + q4.w * k4.w;
#pragma unroll
        for (int o = 8; o; o >>= 1) d += __shfl_xor_sync(hmask, d, o);
        float pe = __expf((d + w * qwe) * 0.125f);   // 1/sqrt(64)

        s   += pe;
        spw += pe * w;
        a0  += pe * v4.x;
        a1  += pe * v4.y;
        a2  += pe * v4.z;
        a3  += pe * v4.w;
    }

    s   += __shfl_xor_sync(0xffffffffu, s,   16);
    spw += __shfl_xor_sync(0xffffffffu, spw, 16);
    a0  += __shfl_xor_sync(0xffffffffu, a0,  16);
    a1  += __shfl_xor_sync(0xffffffffu, a1,  16);
    a2  += __shfl_xor_sync(0xffffffffu, a2,  16);
    a3  += __shfl_xor_sync(0xffffffffu, a3,  16);

    float inv = 1.f / (s + 1e-16f);
    const float4 sk = *(const float4*)&g_s[dst * 64 + f0];
    float o0 = fmaxf((a0 + spw * we4.x) * inv + sk.x, 0.f);
    float o1 = fmaxf((a1 + spw * we4.y) * inv + sk.y, 0.f);
    float o2 = fmaxf((a2 + spw * we4.z) * inv + sk.z, 0.f);
    float o3 = fmaxf((a3 + spw * we4.w) * inv + sk.w, 0.f);

    if (half == 0) {
        if (do_pool) {
            int g = batch[dst];
            float* pp = &g_pool[g * 64 + f0];
            atomicAdd(pp,     o0);
            atomicAdd(pp + 1, o1);
            atomicAdd(pp + 2, o2);
            atomicAdd(pp + 3, o3);
        } else {
            float4 o; o.x = o0; o.y = o1; o.z = o2; o.w = o3;
            *(float4*)&g_h[dst * 64 + f0] = o;
        }
    }
}

// ---------------- classifier head ------------------------------------------
__global__ void final_kernel(const float* __restrict__ Wl,
                             const float* __restrict__ bl,
                             float* __restrict__ out) {
    int t = threadIdx.x;  // 512 = GG * 2
    int g = t >> 1, c = t & 1;
    float cnt = fmaxf(g_pcnt[g], 1.f);
    float sum = 0.f;
    for (int f = 0; f < 64; f++)
        sum += g_pool[g * 64 + f] * Wl[f * 2 + c];
    out[g * 2 + c] = sum / cnt + bl[c];
}

// ---------------- launch ----------------------------------------------------
// Side stream + events created once on the first (uncaptured correctness)
// call; capture sees only kernel launches + event fork/join (graph-legal).
static cudaStream_t g_s2 = 0;
static cudaEvent_t  g_e1 = 0, g_e2 = 0;

extern "C" void kernel_launch(void* const* d_in, const int* in_sizes, int n_in,
                              void* d_out, int out_size) {
    const float* x     = (const float*)d_in[0];
    const int*   ei    = (const int*)d_in[1];
    const float* ew    = (const float*)d_in[2];
    const int*   batch = (const int*)d_in[3];
    const float *Wq1 = (const float*)d_in[4],  *bq1 = (const float*)d_in[5];
    const float *Wk1 = (const float*)d_in[6],  *bk1 = (const float*)d_in[7];
    const float *Wv1 = (const float*)d_in[8],  *bv1 = (const float*)d_in[9];
    const float *We1 = (const float*)d_in[10];
    const float *Ws1 = (const float*)d_in[11], *bs1 = (const float*)d_in[12];
    const float *Wq2 = (const float*)d_in[13], *bq2 = (const float*)d_in[14];
    const float *Wk2 = (const float*)d_in[15], *bk2 = (const float*)d_in[16];
    const float *Wv2 = (const float*)d_in[17], *bv2 = (const float*)d_in[18];
    const float *We2 = (const float*)d_in[19];
    const float *Ws2 = (const float*)d_in[20], *bs2 = (const float*)d_in[21];
    const float *Wl  = (const float*)d_in[22], *bl  = (const float*)d_in[23];
    float* out = (float*)d_out;

    if (!g_s2) {
        cudaStreamCreateWithFlags(&g_s2, cudaStreamNonBlocking);
        cudaEventCreateWithFlags(&g_e1, cudaEventDisableTiming);
        cudaEventCreateWithFlags(&g_e2, cudaEventDisableTiming);
        cudaFuncSetAttribute(gemm4_kernel,
                             cudaFuncAttributeMaxDynamicSharedMemorySize,
                             GEMM_SMEM);
    }

    const int GEMM_BLOCKS  = (NN + 63) / 64;                     // 782
    const int COUNT_BLOCKS = (EE / 4 + NN / 4 + 255) / 256;      // 831
    const int SCAT_BLOCKS  = (EE / 4 + 255) / 256;               // 782
    const int AGG_BLOCKS   = (NN * 32 + 255) / 256;              // 6250

    // Fork: gemm1 (reads only x/W) runs on the side stream concurrent with
    // the CSR build chain on the main stream; join before edge_agg L1.
    cudaEventRecord(g_e1, 0);
    cudaStreamWaitEvent(g_s2, g_e1, 0);
    gemm4_kernel<<<GEMM_BLOCKS, 512, GEMM_SMEM, g_s2>>>(
        x, 0, Wq1, bq1, Wk1, bk1, Wv1, bv1, Ws1, bs1);
    cudaEventRecord(g_e2, g_s2);

    // CSR build on the main stream
    zero_kernel<<<69, 256>>>();
    count_kernel<<<COUNT_BLOCKS, 256>>>(ei, batch);
    scanA_kernel<<<SC_NB, 256>>>();
    scanB_kernel<<<1, 64>>>();
    scanC_kernel<<<SC_NB, 256>>>();
    scatter_kernel<<<SCAT_BLOCKS, 256>>>(ei, ew);

    // Join, then layer-1 aggregation
    cudaStreamWaitEvent(0, g_e2, 0);
    edge_agg_kernel<<<AGG_BLOCKS, 256>>>(We1, 0, batch);

    // Layer 2 (input = g_h; pooling fused, h never materialized)
    gemm4_kernel<<<GEMM_BLOCKS, 512, GEMM_SMEM>>>(x, 1, Wq2, bq2, Wk2, bk2,
                                                  Wv2, bv2, Ws2, bs2);
    edge_agg_kernel<<<AGG_BLOCKS, 256>>>(We2, 1, batch);

    // Head
    final_kernel<<<1, 512>>>(Wl, bl, out);
}

// round 17
// speedup vs baseline: 1.5420x; 1.0163x over previous
#include <cuda_runtime.h>

// Problem constants (fixed by the reference)
#define NN 50000
#define EE 800000
#define HH 64
#define GG 256

#define SC_NB 52                 // scan blocks
#define CNT_PAD (SC_NB * 1024)   // 53248 (padded count array)

typedef unsigned long long u64;

// ---------------- scratch (device globals; no runtime allocation) ----------
__device__ float g_q[NN * HH];
__device__ float g_k[NN * HH];
__device__ float g_v[NN * HH];
__device__ float g_s[NN * HH];   // skip = in @ Ws + bs
__device__ float g_h[NN * HH];   // layer-1 output

__device__ int   g_cnt[CNT_PAD];      // per-dst edge counts (padded)
__device__ int   g_off[CNT_PAD + 4];  // CSR row offsets
__device__ int   g_off2[CNT_PAD + 4]; // scatter cursors (copy of offsets)
__device__ int   g_bsum[SC_NB];       // scan phase A partials
__device__ int   g_bbase[SC_NB];      // scan phase B bases
__device__ int   g_csrc[EE];          // CSR: src node per edge slot
__device__ float g_cw[EE];            // CSR: edge weight per edge slot

__device__ float g_pool[GG * HH];
__device__ float g_pcnt[GG];

// ---------------- packed f32x2 helpers --------------------------------------
__device__ __forceinline__ u64 pack2(float lo, float hi) {
    u64 r; asm("mov.b64 %0, {%1, %2};" : "=l"(r) : "f"(lo), "f"(hi)); return r;
}
__device__ __forceinline__ void fma2(u64& d, u64 a, u64 b) {
    asm("fma.rn.f32x2 %0, %1, %2, %0;" : "+l"(d) : "l"(a), "l"(b));
}
__device__ __forceinline__ float2 unpack2(u64 v) {
    float2 r; asm("mov.b64 {%0, %1}, %2;" : "=f"(r.x), "=f"(r.y) : "l"(v)); return r;
}

// ---------------- zero scratch (vectorized) ---------------------------------
__global__ void zero_kernel() {
    int i = blockIdx.x * blockDim.x + threadIdx.x;
    const int C4 = CNT_PAD / 4;          // 13312
    const int P4 = (GG * HH) / 4;        // 4096
    const int T  = C4 + P4 + GG / 4;     // 17472
    for (; i < T; i += gridDim.x * blockDim.x) {
        if (i < C4)           ((int4*)g_cnt)[i] = make_int4(0, 0, 0, 0);
        else if (i < C4 + P4) ((float4*)g_pool)[i - C4] = make_float4(0, 0, 0, 0);
        else                  ((float4*)g_pcnt)[i - C4 - P4] = make_float4(0, 0, 0, 0);
    }
}

// ---------------- CSR counts + graph node counts (int4 loads) --------------
__global__ void count_kernel(const int* __restrict__ ei,
                             const int* __restrict__ batch) {
    int t = blockIdx.x * blockDim.x + threadIdx.x;
    const int NE4 = EE / 4;       // 200000
    const int NB4 = NN / 4;       // 12500
    if (t < NE4) {
        int4 d = ((const int4*)(ei + EE))[t];
        atomicAdd(&g_cnt[d.x], 1);
        atomicAdd(&g_cnt[d.y], 1);
        atomicAdd(&g_cnt[d.z], 1);
        atomicAdd(&g_cnt[d.w], 1);
    } else if (t < NE4 + NB4) {
        int4 b = ((const int4*)batch)[t - NE4];
        atomicAdd(&g_pcnt[b.x], 1.f);
        atomicAdd(&g_pcnt[b.y], 1.f);
        atomicAdd(&g_pcnt[b.z], 1.f);
        atomicAdd(&g_pcnt[b.w], 1.f);
    }
}

// ---------------- parallel exclusive scan: 3 phases --------------------------
__global__ void scanA_kernel() {
    __shared__ int wsum[8];
    const int b = blockIdx.x, t = threadIdx.x;
    int4 v = ((const int4*)g_cnt)[b * 256 + t];
    int s = v.x + v.y + v.z + v.w;
#pragma unroll
    for (int o = 16; o; o >>= 1) s += __shfl_xor_sync(0xffffffffu, s, o);
    if ((t & 31) == 0) wsum[t >> 5] = s;
    __syncthreads();
    if (t < 8) {
        int x = wsum[t];
#pragma unroll
        for (int o = 4; o; o >>= 1) x += __shfl_xor_sync(0xffu, x, o);
        if (t == 0) g_bsum[b] = x;
    }
}

__global__ void scanB_kernel() {
    __shared__ int sh[64];
    const int t = threadIdx.x;
    int v = (t < SC_NB) ? g_bsum[t] : 0;
    sh[t] = v;
    __syncthreads();
    for (int o = 1; o < 64; o <<= 1) {
        int u = (t >= o) ? sh[t - o] : 0;
        __syncthreads();
        sh[t] += u;
        __syncthreads();
    }
    if (t < SC_NB) g_bbase[t] = sh[t] - v;   // exclusive
}

__global__ void scanC_kernel() {
    __shared__ int wpre[8];
    const int b = blockIdx.x, t = threadIdx.x;
    const int lane = t & 31, w = t >> 5;
    int4 v = ((const int4*)g_cnt)[b * 256 + t];
    int s = v.x + v.y + v.z + v.w;

    int ps = s;  // inclusive warp scan of per-thread sums
#pragma unroll
    for (int o = 1; o < 32; o <<= 1) {
        int u = __shfl_up_sync(0xffffffffu, ps, o);
        if (lane >= o) ps += u;
    }
    if (lane == 31) wpre[w] = ps;
    __syncthreads();
    if (t < 8) {
        int x = wpre[t];
        int px = x;
#pragma unroll
        for (int o = 1; o < 8; o <<= 1) {
            int u = __shfl_up_sync(0xffu, px, o);
            if (t >= o) px += u;
        }
        wpre[t] = px - x;
    }
    __syncthreads();

    int base = g_bbase[b] + wpre[w] + (ps - s);
    int4 o;
    o.x = base;
    o.y = base + v.x;
    o.z = o.y + v.y;
    o.w = o.z + v.z;
    ((int4*)g_off)[b * 256 + t]  = o;
    ((int4*)g_off2)[b * 256 + t] = o;
    if (b == SC_NB - 1 && t == 255) g_off[CNT_PAD] = o.w + v.w;
}

// ---------------- scatter into CSR (cursor = offset copy) -------------------
__global__ void scatter_kernel(const int* __restrict__ ei,
                               const float* __restrict__ ew) {
    int t = blockIdx.x * blockDim.x + threadIdx.x;
    if (t >= EE / 4) return;
    int4   s4 = ((const int4*)ei)[t];
    int4   d4 = ((const int4*)(ei + EE))[t];
    float4 w4 = ((const float4*)ew)[t];
    int p;
    p = atomicAdd(&g_off2[d4.x], 1); g_csrc[p] = s4.x; g_cw[p] = w4.x;
    p = atomicAdd(&g_off2[d4.y], 1); g_csrc[p] = s4.y; g_cw[p] = w4.y;
    p = atomicAdd(&g_off2[d4.z], 1); g_csrc[p] = s4.z; g_cw[p] = w4.z;
    p = atomicAdd(&g_off2[d4.w], 1); g_csrc[p] = s4.w; g_cw[p] = w4.w;
}

// ---------------- fused 4-matrix GEMM (packed f32x2 FFMA, 512 thr) ----------
// R11-verbatim: the measured-best GEMM (58us). Tile: 64 nodes x 256 feats.
// 512 threads; thread = 8 nodes x 4 feats. 2 blocks/SM -> 32 warps/SM.
#define GEMM_SMEM (64 * 256 * 4 + 64 * 68 * 4)   // 82944 bytes

__global__ __launch_bounds__(512, 2) void gemm4_kernel(
    const float* __restrict__ xin, int use_h,
    const float* __restrict__ Wq, const float* __restrict__ bq,
    const float* __restrict__ Wk, const float* __restrict__ bk,
    const float* __restrict__ Wv, const float* __restrict__ bv,
    const float* __restrict__ Ws, const float* __restrict__ bs) {
    extern __shared__ float smem[];
    float* Wsh = smem;              // [64][256]: q|k|v|s concat per k-row
    float* xst = smem + 64 * 256;   // [64][68]  (transposed x tile, padded)

    const float* in = use_h ? g_h : xin;
    const int t   = threadIdx.x;
    const int n0g = blockIdx.x * 64;

    for (int i = t; i < 4096; i += 512) {
        int kk = i >> 6, f = i & 63;
        float* row = &Wsh[kk * 256];
        row[f]       = Wq[i];
        row[64 + f]  = Wk[i];
        row[128 + f] = Wv[i];
        row[192 + f] = Ws[i];
    }
    for (int i = t; i < 4096; i += 512) {
        int nl = i >> 6, kk = i & 63;
        int n = n0g + nl;
        xst[kk * 68 + nl] = (n < NN) ? in[n * 64 + kk] : 0.f;
    }
    __syncthreads();

    const int warp = t >> 5;
    const int l    = t & 31;
    const int fgrp = warp & 1;            // 0: q|k feats, 1: v|s feats
    const int fA   = fgrp * 128 + l * 4;  // position in 256-wide concat
    const int n0   = (warp >> 1) * 8;     // node octet

    u64 acc2[8][2];
#pragma unroll
    for (int i = 0; i < 8; i++) { acc2[i][0] = 0ULL; acc2[i][1] = 0ULL; }

#pragma unroll 4
    for (int kk = 0; kk < 64; kk++) {
        const float* xr = &xst[kk * 68 + n0];
        float4 xa = *(const float4*)xr;
        float4 xb = *(const float4*)(xr + 4);
        ulonglong2 w2 = *(const ulonglong2*)(&Wsh[kk * 256] + fA);
        float xv[8] = {xa.x, xa.y, xa.z, xa.w, xb.x, xb.y, xb.z, xb.w};
#pragma unroll
        for (int i = 0; i < 8; i++) {
            u64 xd = pack2(xv[i], xv[i]);
            fma2(acc2[i][0], xd, w2.x);
            fma2(acc2[i][1], xd, w2.y);
        }
    }

    const int fo = (l & 15) * 4;
    float* op;  const float* bp;
    if (fgrp == 0) { if (l < 16) { op = g_q; bp = bq; } else { op = g_k; bp = bk; } }
    else           { if (l < 16) { op = g_v; bp = bv; } else { op = g_s; bp = bs; } }
    float4 bias = *(const float4*)&bp[fo];

#pragma unroll
    for (int i = 0; i < 8; i++) {
        int n = n0g + n0 + i;
        if (n < NN) {
            float2 p0 = unpack2(acc2[i][0]);
            float2 p1 = unpack2(acc2[i][1]);
            float4 r;
            r.x = p0.x + bias.x; r.y = p0.y + bias.y;
            r.z = p1.x + bias.z; r.w = p1.y + bias.w;
            *(float4*)&op[n * 64 + fo] = r;
        }
    }
}

// ---------------- edge aggregation: half-warp per edge, 2-way ILP -----------
// Warp owns one dst; each 16-lane half processes its edges with float4 loads.
// Direct softmax (no max subtraction; logits O(1)) means accumulators are
// plain sums -> two INDEPENDENT accumulator sets per half (edges i and i+2
// interleaved) double the gather->reduce->exp chains in flight, hiding L2
// latency. Intra-half shuffles use the half's member mask; merges are plain
// adds after reconvergence.
__global__ __launch_bounds__(256) void edge_agg_kernel(
    const float* __restrict__ We, int do_pool, const int* __restrict__ batch) {
    int wid  = (blockIdx.x * blockDim.x + threadIdx.x) >> 5;
    int lane = threadIdx.x & 31;
    if (wid >= NN) return;
    const int dst  = wid;
    const int half = lane >> 4;
    const int f0   = (lane & 15) * 4;
    const unsigned hmask = half ? 0xFFFF0000u : 0x0000FFFFu;

    const float4 q4  = *(const float4*)&g_q[dst * 64 + f0];
    const float4 we4 = *(const float4*)&We[f0];

    float p = q4.x * we4.x + q4.y * we4.y + q4.z * we4.z + q4.w * we4.w;
#pragma unroll
    for (int o = 8; o; o >>= 1) p += __shfl_xor_sync(hmask, p, o);
    const float qwe = p;

    const int i0 = g_off[dst], i1 = g_off[dst + 1];
    float s0 = 0.f, w0s = 0.f, a0 = 0.f, a1 = 0.f, a2 = 0.f, a3 = 0.f;
    float s1 = 0.f, w1s = 0.f, b0 = 0.f, b1 = 0.f, b2 = 0.f, b3 = 0.f;

    int i = i0 + half;
    // pairs: edges i (set0) and i+2 (set1), fully independent chains
    for (; i + 2 < i1; i += 4) {
        int   srcA = g_csrc[i];
        int   srcB = g_csrc[i + 2];
        float wA   = g_cw[i];
        float wB   = g_cw[i + 2];
        const float4 kA = *(const float4*)&g_k[srcA * 64 + f0];
        const float4 kB = *(const float4*)&g_k[srcB * 64 + f0];
        const float4 vA = *(const float4*)&g_v[srcA * 64 + f0];
        const float4 vB = *(const float4*)&g_v[srcB * 64 + f0];

        float dA = q4.x * kA.x + q4.y * kA.y + q4.z * kA.z + q4.w * kA.w;
        float dB = q4.x * kB.x + q4.y * kB.y + q4.z * kB.z + q4.w * kB.w;
#pragma unroll
        for (int o = 8; o; o >>= 1) {
            dA += __shfl_xor_sync(hmask, dA, o);
            dB += __shfl_xor_sync(hmask, dB, o);
        }
        float peA = __expf((dA + wA * qwe) * 0.125f);
        float peB = __expf((dB + wB * qwe) * 0.125f);

        s0 += peA;  w0s += peA * wA;
        a0 += peA * vA.x;  a1 += peA * vA.y;
        a2 += peA * vA.z;  a3 += peA * vA.w;
        s1 += peB;  w1s += peB * wB;
        b0 += peB * vB.x;  b1 += peB * vB.y;
        b2 += peB * vB.z;  b3 += peB * vB.w;
    }
    if (i < i1) {
        int   src = g_csrc[i];
        float w   = g_cw[i];
        const float4 k4 = *(const float4*)&g_k[src * 64 + f0];
        const float4 v4 = *(const float4*)&g_v[src * 64 + f0];
        float d = q4.x * k4.x + q4.y * k4.y + q4.z * k4.z + q4.w * k4.w;
#pragma unroll
        for (int o = 8; o; o >>= 1) d += __shfl_xor_sync(hmask, d, o);
        float pe = __expf((d + w * qwe) * 0.125f);
        s0 += pe;  w0s += pe * w;
        a0 += pe * v4.x;  a1 += pe * v4.y;
        a2 += pe * v4.z;  a3 += pe * v4.w;
    }

    // merge the two ILP sets, then the two halves
    float s   = s0 + s1;
    float spw = w0s + w1s;
    a0 += b0;  a1 += b1;  a2 += b2;  a3 += b3;

    s   += __shfl_xor_sync(0xffffffffu, s,   16);
    spw += __shfl_xor_sync(0xffffffffu, spw, 16);
    a0  += __shfl_xor_sync(0xffffffffu, a0,  16);
    a1  += __shfl_xor_sync(0xffffffffu, a1,  16);
    a2  += __shfl_xor_sync(0xffffffffu, a2,  16);
    a3  += __shfl_xor_sync(0xffffffffu, a3,  16);

    float inv = 1.f / (s + 1e-16f);
    const float4 sk = *(const float4*)&g_s[dst * 64 + f0];
    float o0 = fmaxf((a0 + spw * we4.x) * inv + sk.x, 0.f);
    float o1 = fmaxf((a1 + spw * we4.y) * inv + sk.y, 0.f);
    float o2 = fmaxf((a2 + spw * we4.z) * inv + sk.z, 0.f);
    float o3 = fmaxf((a3 + spw * we4.w) * inv + sk.w, 0.f);

    if (half == 0) {
        if (do_pool) {
            int g = batch[dst];
            float* pp = &g_pool[g * 64 + f0];
            atomicAdd(pp,     o0);
            atomicAdd(pp + 1, o1);
            atomicAdd(pp + 2, o2);
            atomicAdd(pp + 3, o3);
        } else {
            float4 o; o.x = o0; o.y = o1; o.z = o2; o.w = o3;
            *(float4*)&g_h[dst * 64 + f0] = o;
        }
    }
}

// ---------------- classifier head ------------------------------------------
__global__ void final_kernel(const float* __restrict__ Wl,
                             const float* __restrict__ bl,
                             float* __restrict__ out) {
    int t = threadIdx.x;  // 512 = GG * 2
    int g = t >> 1, c = t & 1;
    float cnt = fmaxf(g_pcnt[g], 1.f);
    float sum = 0.f;
    for (int f = 0; f < 64; f++)
        sum += g_pool[g * 64 + f] * Wl[f * 2 + c];
    out[g * 2 + c] = sum / cnt + bl[c];
}

// ---------------- launch ----------------------------------------------------
// Side stream + events created once on the first (uncaptured correctness)
// call; capture sees only kernel launches + event fork/join (graph-legal).
static cudaStream_t g_s2 = 0;
static cudaEvent_t  g_e1 = 0, g_e2 = 0;

extern "C" void kernel_launch(void* const* d_in, const int* in_sizes, int n_in,
                              void* d_out, int out_size) {
    const float* x     = (const float*)d_in[0];
    const int*   ei    = (const int*)d_in[1];
    const float* ew    = (const float*)d_in[2];
    const int*   batch = (const int*)d_in[3];
    const float *Wq1 = (const float*)d_in[4],  *bq1 = (const float*)d_in[5];
    const float *Wk1 = (const float*)d_in[6],  *bk1 = (const float*)d_in[7];
    const float *Wv1 = (const float*)d_in[8],  *bv1 = (const float*)d_in[9];
    const float *We1 = (const float*)d_in[10];
    const float *Ws1 = (const float*)d_in[11], *bs1 = (const float*)d_in[12];
    const float *Wq2 = (const float*)d_in[13], *bq2 = (const float*)d_in[14];
    const float *Wk2 = (const float*)d_in[15], *bk2 = (const float*)d_in[16];
    const float *Wv2 = (const float*)d_in[17], *bv2 = (const float*)d_in[18];
    const float *We2 = (const float*)d_in[19];
    const float *Ws2 = (const float*)d_in[20], *bs2 = (const float*)d_in[21];
    const float *Wl  = (const float*)d_in[22], *bl  = (const float*)d_in[23];
    float* out = (float*)d_out;

    if (!g_s2) {
        cudaStreamCreateWithFlags(&g_s2, cudaStreamNonBlocking);
        cudaEventCreateWithFlags(&g_e1, cudaEventDisableTiming);
        cudaEventCreateWithFlags(&g_e2, cudaEventDisableTiming);
        cudaFuncSetAttribute(gemm4_kernel,
                             cudaFuncAttributeMaxDynamicSharedMemorySize,
                             GEMM_SMEM);
    }

    const int GEMM_BLOCKS  = (NN + 63) / 64;                     // 782
    const int COUNT_BLOCKS = (EE / 4 + NN / 4 + 255) / 256;      // 831
    const int SCAT_BLOCKS  = (EE / 4 + 255) / 256;               // 782
    const int AGG_BLOCKS   = (NN * 32 + 255) / 256;              // 6250

    // Fork: gemm1 (reads only x/W) runs on the side stream concurrent with
    // the CSR build chain on the main stream; join before edge_agg L1.
    cudaEventRecord(g_e1, 0);
    cudaStreamWaitEvent(g_s2, g_e1, 0);
    gemm4_kernel<<<GEMM_BLOCKS, 512, GEMM_SMEM, g_s2>>>(
        x, 0, Wq1, bq1, Wk1, bk1, Wv1, bv1, Ws1, bs1);
    cudaEventRecord(g_e2, g_s2);

    // CSR build on the main stream
    zero_kernel<<<69, 256>>>();
    count_kernel<<<COUNT_BLOCKS, 256>>>(ei, batch);
    scanA_kernel<<<SC_NB, 256>>>();
    scanB_kernel<<<1, 64>>>();
    scanC_kernel<<<SC_NB, 256>>>();
    scatter_kernel<<<SCAT_BLOCKS, 256>>>(ei, ew);

    // Join, then layer-1 aggregation
    cudaStreamWaitEvent(0, g_e2, 0);
    edge_agg_kernel<<<AGG_BLOCKS, 256>>>(We1, 0, batch);

    // Layer 2 (input = g_h; pooling fused, h never materialized)
    gemm4_kernel<<<GEMM_BLOCKS, 512, GEMM_SMEM>>>(x, 1, Wq2, bq2, Wk2, bk2,
                                                  Wv2, bv2, Ws2, bs2);
    edge_agg_kernel<<<AGG_BLOCKS, 256>>>(We2, 1, batch);

    // Head
    final_kernel<<<1, 512>>>(Wl, bl, out);
}